// round 14
// baseline (speedup 1.0000x reference)
#include <cuda_runtime.h>
#include <cuda_bf16.h>
#include <math.h>
#include <stdint.h>

#define BATCH 16
#define CIN   256
#define HW    4096      // 64*64
#define DOWN  1024      // 32*32
#define C8    32
#define C2    128
#define MCONV 192       // 32 + 32 + 128
#define NCHUNK 64       // l-chunks for column sum partials (64 rows each)

// ---------------- scratch (device globals; no allocation allowed) ----------------
__device__ float g_w   [MCONV * CIN];
__device__ float g_bias[MCONV];
__device__ float g_q   [BATCH * C8 * HW];
__device__ float g_kp  [BATCH * C8 * DOWN];
__device__ float g_vp  [BATCH * C2 * DOWN];
__device__ __nv_bfloat16 g_attn[(size_t)BATCH * HW * DOWN];  // 134 MB: P = exp(logit)
__device__ float g_ps  [BATCH * NCHUNK * DOWN];              // partial sums of P
__device__ float g_csumr[BATCH * DOWN];
__device__ float g_app [BATCH * HW * C2];

// ---------------- helpers --------------------------------------------------------
__device__ __forceinline__ uint32_t f2tf32(float v) {
    uint32_t r;
    asm("cvt.rna.tf32.f32 %0, %1;" : "=r"(r) : "f"(v));
    return r;
}
__device__ __forceinline__ void mma_tf32(float* d, const uint32_t* a, const uint32_t* b) {
    asm volatile(
        "mma.sync.aligned.m16n8k8.row.col.f32.tf32.tf32.f32 "
        "{%0,%1,%2,%3}, {%4,%5,%6,%7}, {%8,%9}, {%0,%1,%2,%3};"
        : "+f"(d[0]), "+f"(d[1]), "+f"(d[2]), "+f"(d[3])
        : "r"(a[0]), "r"(a[1]), "r"(a[2]), "r"(a[3]), "r"(b[0]), "r"(b[1]));
}
__device__ __forceinline__ void mma_bf16(float* d, const uint32_t* a, const uint32_t* b) {
    asm volatile(
        "mma.sync.aligned.m16n8k16.row.col.f32.bf16.bf16.f32 "
        "{%0,%1,%2,%3}, {%4,%5,%6,%7}, {%8,%9}, {%0,%1,%2,%3};"
        : "+f"(d[0]), "+f"(d[1]), "+f"(d[2]), "+f"(d[3])
        : "r"(a[0]), "r"(a[1]), "r"(a[2]), "r"(a[3]), "r"(b[0]), "r"(b[1]));
}
// split v into bf16 hi + bf16 lo (v ~= hi + lo, residual ~ v * 2^-18)
__device__ __forceinline__ void split_bf16(float v, __nv_bfloat16& hi, __nv_bfloat16& lo) {
    hi = __float2bfloat16_rn(v);
    lo = __float2bfloat16_rn(v - __bfloat162float(hi));
}
#define FU(x) __float_as_uint(x)

// ---------------- K0: pack conv weights ------------------------------------------
__global__ void k_pack(const float* __restrict__ qw, const float* __restrict__ qb,
                       const float* __restrict__ kw, const float* __restrict__ kb,
                       const float* __restrict__ vw, const float* __restrict__ vb) {
    int i = blockIdx.x * 256 + threadIdx.x;
    if (i < MCONV * CIN) {
        int r = i >> 8, c = i & 255;
        float v;
        if (r < 32)      v = qw[r * CIN + c];
        else if (r < 64) v = kw[(r - 32) * CIN + c];
        else             v = vw[(r - 64) * CIN + c];
        g_w[i] = v;
    }
    if (i < MCONV)
        g_bias[i] = (i < 32) ? qb[i] : (i < 64) ? kb[i - 32] : vb[i - 64];
}

// ---------------- K1: fused q/k/v convs + INLINE 2x2 MAXPOOL for k/v -------------
__global__ __launch_bounds__(256) void k_conv_mma(const float* __restrict__ x) {
    __shared__ float sA[64][36];    // W tile [m][k]
    __shared__ float sB[32][136];   // X tile [k][n]
    __shared__ float sPool[64][36]; // lower-half pair-max exchange

    const int b  = blockIdx.z;
    const int m0 = blockIdx.y * 64;
    const int n0 = blockIdx.x * 128;
    const float* X = x + (size_t)b * CIN * HW;

    const int tid  = threadIdx.x;
    const int wid  = tid >> 5;
    const int lane = tid & 31;
    const int qid  = lane >> 2;
    const int qtr  = lane & 3;
    const int wm   = (wid >> 2) * 32;
    const int wn   = (wid & 3) * 32;

    float acc[2][4][4] = {};

    for (int k0 = 0; k0 < CIN; k0 += 32) {
        #pragma unroll
        for (int it = 0; it < 2; it++) {
            int f = tid + it * 256;
            int m = f >> 3, k4 = (f & 7) * 4;
            float4 a4 = *(const float4*)&g_w[(m0 + m) * CIN + k0 + k4];
            uint32_t* dp = (uint32_t*)&sA[m][k4];
            dp[0] = f2tf32(a4.x); dp[1] = f2tf32(a4.y);
            dp[2] = f2tf32(a4.z); dp[3] = f2tf32(a4.w);
        }
        #pragma unroll
        for (int it = 0; it < 4; it++) {
            int f = tid + it * 256;
            int kk = f >> 5, n4 = (f & 31) * 4;
            float4 b4 = *(const float4*)&X[(size_t)(k0 + kk) * HW + n0 + n4];
            uint32_t* dp = (uint32_t*)&sB[kk][n4];
            dp[0] = f2tf32(b4.x); dp[1] = f2tf32(b4.y);
            dp[2] = f2tf32(b4.z); dp[3] = f2tf32(b4.w);
        }
        __syncthreads();

        #pragma unroll
        for (int ks = 0; ks < 4; ks++) {
            const int kk = ks * 8;
            uint32_t af[2][4], bf[4][2];
            #pragma unroll
            for (int ma = 0; ma < 2; ma++) {
                int r = wm + ma * 16 + qid;
                af[ma][0] = FU(sA[r    ][kk + qtr]);
                af[ma][1] = FU(sA[r + 8][kk + qtr]);
                af[ma][2] = FU(sA[r    ][kk + qtr + 4]);
                af[ma][3] = FU(sA[r + 8][kk + qtr + 4]);
            }
            #pragma unroll
            for (int na = 0; na < 4; na++) {
                int c = wn + na * 8 + qid;
                bf[na][0] = FU(sB[kk + qtr    ][c]);
                bf[na][1] = FU(sB[kk + qtr + 4][c]);
            }
            #pragma unroll
            for (int ma = 0; ma < 2; ma++)
                #pragma unroll
                for (int na = 0; na < 4; na++)
                    mma_tf32(acc[ma][na], af[ma], bf[na]);
        }
        __syncthreads();
    }

    // ---- epilogue phase 1: q direct stores + lower-half (h0 row) pool partials --
    #pragma unroll
    for (int ma = 0; ma < 2; ma++) {
        #pragma unroll
        for (int half = 0; half < 2; half++) {
            int rl = wm + ma * 16 + qid + half * 8;   // row in tile 0..63
            int m  = m0 + rl;
            float bias = g_bias[m];
            if (m < 32) {
                float* dst = g_q + ((size_t)b * C8 + m) * HW;
                #pragma unroll
                for (int na = 0; na < 4; na++) {
                    int c = n0 + wn + na * 8 + 2 * qtr;
                    float2 o;
                    o.x = acc[ma][na][half * 2 + 0] + bias;
                    o.y = acc[ma][na][half * 2 + 1] + bias;
                    *(float2*)&dst[c] = o;
                }
            } else if (wn < 64) {
                #pragma unroll
                for (int na = 0; na < 4; na++) {
                    float vx = acc[ma][na][half * 2 + 0] + bias;
                    float vy = acc[ma][na][half * 2 + 1] + bias;
                    sPool[rl][(wn >> 1) + na * 4 + qtr] = fmaxf(vx, vy);
                }
            }
        }
    }
    __syncthreads();

    // ---- epilogue phase 2: upper-half (h0+1 row) combine + pooled store ---------
    if (wn >= 64) {
        const int p0 = (n0 >> 7) * 32;   // ph * 32
        #pragma unroll
        for (int ma = 0; ma < 2; ma++) {
            #pragma unroll
            for (int half = 0; half < 2; half++) {
                int rl = wm + ma * 16 + qid + half * 8;
                int m  = m0 + rl;
                if (m < 32) continue;
                float bias = g_bias[m];
                float* dst = (m < 64)
                    ? g_kp + ((size_t)b * C8 + (m - 32)) * DOWN
                    : g_vp + ((size_t)b * C2 + (m - 64)) * DOWN;
                #pragma unroll
                for (int na = 0; na < 4; na++) {
                    int pw = ((wn - 64) >> 1) + na * 4 + qtr;
                    float vx = acc[ma][na][half * 2 + 0] + bias;
                    float vy = acc[ma][na][half * 2 + 1] + bias;
                    float pm = fmaxf(fmaxf(vx, vy), sPool[rl][pw]);
                    dst[p0 + pw] = pm;
                }
            }
        }
    }
}

// ---------------- K3a: P = exp(Q @ K^T) via split-bf16 mma, tile 64l x 128j ------
// Virtual K=96: Q_ext = [hi | lo | hi], K_ext = [bh | bh | bl]
// => hi*bh + lo*bh + hi*bl ~= fp32-accurate product (residual ~2^-18).
__global__ __launch_bounds__(256) void k_attn_mma() {
    __shared__ __nv_bfloat16 sQ[64][104];    // [l][K_ext], pad 104
    __shared__ __nv_bfloat16 sK[128][104];   // [j][K_ext]

    const int b  = blockIdx.z;
    const int l0 = blockIdx.y * 64;
    const int j0 = blockIdx.x * 128;

    const float* Q  = g_q  + (size_t)b * (C8 * HW);    // viewed [4096][32]
    const float* Km = g_kp + (size_t)b * (C8 * DOWN);  // viewed [1024][32]

    const int tid  = threadIdx.x;
    const int wid  = tid >> 5;
    const int lane = tid & 31;
    const int qid  = lane >> 2;
    const int qtr  = lane & 3;
    const int wm   = (wid >> 2) * 32;   // 0 or 32
    const int wn   = (wid & 3) * 32;    // 0,32,64,96

    // stage Q: 64x32 fp32 -> hi@[k], lo@[32+k], hi@[64+k]
    #pragma unroll
    for (int it = 0; it < 2; it++) {
        int idx = tid + it * 256;
        int lr = idx >> 3, lc = (idx & 7) * 4;
        float4 v = *(const float4*)&Q[(size_t)(l0 + lr) * 32 + lc];
        __nv_bfloat16 h, l;
        split_bf16(v.x, h, l); sQ[lr][lc + 0] = h; sQ[lr][32 + lc + 0] = l; sQ[lr][64 + lc + 0] = h;
        split_bf16(v.y, h, l); sQ[lr][lc + 1] = h; sQ[lr][32 + lc + 1] = l; sQ[lr][64 + lc + 1] = h;
        split_bf16(v.z, h, l); sQ[lr][lc + 2] = h; sQ[lr][32 + lc + 2] = l; sQ[lr][64 + lc + 2] = h;
        split_bf16(v.w, h, l); sQ[lr][lc + 3] = h; sQ[lr][32 + lc + 3] = l; sQ[lr][64 + lc + 3] = h;
    }
    // stage K: 128x32 fp32 -> bh@[k], bh@[32+k], bl@[64+k]
    #pragma unroll
    for (int it = 0; it < 4; it++) {
        int idx = tid + it * 256;
        int jr = idx >> 3, jc = (idx & 7) * 4;
        float4 v = *(const float4*)&Km[(size_t)(j0 + jr) * 32 + jc];
        __nv_bfloat16 h, l;
        split_bf16(v.x, h, l); sK[jr][jc + 0] = h; sK[jr][32 + jc + 0] = h; sK[jr][64 + jc + 0] = l;
        split_bf16(v.y, h, l); sK[jr][jc + 1] = h; sK[jr][32 + jc + 1] = h; sK[jr][64 + jc + 1] = l;
        split_bf16(v.z, h, l); sK[jr][jc + 2] = h; sK[jr][32 + jc + 2] = h; sK[jr][64 + jc + 2] = l;
        split_bf16(v.w, h, l); sK[jr][jc + 3] = h; sK[jr][32 + jc + 3] = h; sK[jr][64 + jc + 3] = l;
    }
    __syncthreads();

    float acc[2][4][4] = {};
    #pragma unroll
    for (int ks = 0; ks < 6; ks++) {
        const int kb = ks * 16;
        uint32_t bfr[4][2];
        #pragma unroll
        for (int na = 0; na < 4; na++) {
            int c = wn + na * 8 + qid;
            bfr[na][0] = *(const uint32_t*)&sK[c][kb + qtr * 2];
            bfr[na][1] = *(const uint32_t*)&sK[c][kb + 8 + qtr * 2];
        }
        #pragma unroll
        for (int ma = 0; ma < 2; ma++) {
            int r = wm + ma * 16 + qid;
            uint32_t af[4];
            af[0] = *(const uint32_t*)&sQ[r    ][kb + qtr * 2];
            af[1] = *(const uint32_t*)&sQ[r + 8][kb + qtr * 2];
            af[2] = *(const uint32_t*)&sQ[r    ][kb + 8 + qtr * 2];
            af[3] = *(const uint32_t*)&sQ[r + 8][kb + 8 + qtr * 2];
            #pragma unroll
            for (int na = 0; na < 4; na++)
                mma_bf16(acc[ma][na], af, bfr[na]);
        }
    }

    // epilogue: exp -> bf16 pair stores
    __nv_bfloat16* C = g_attn + ((size_t)b * HW + l0) * DOWN + j0;
    #pragma unroll
    for (int ma = 0; ma < 2; ma++) {
        int r = wm + ma * 16 + qid;
        #pragma unroll
        for (int na = 0; na < 4; na++) {
            int c = wn + na * 8 + 2 * qtr;
            __nv_bfloat162 lo = __floats2bfloat162_rn(__expf(acc[ma][na][0]), __expf(acc[ma][na][1]));
            __nv_bfloat162 hi = __floats2bfloat162_rn(__expf(acc[ma][na][2]), __expf(acc[ma][na][3]));
            *(uint32_t*)&C[(size_t)r * DOWN + c]       = *(uint32_t*)&lo;
            *(uint32_t*)&C[(size_t)(r + 8) * DOWN + c] = *(uint32_t*)&hi;
        }
    }
}

// ---------------- K3b: per-column partial sums of P (pure sum, bf16 in) ----------
__global__ void k_stats1() {
    const int b  = blockIdx.z;
    const int ck = blockIdx.y;
    const int j2 = blockIdx.x * 256 + threadIdx.x;   // column pair 0..511
    const int lsz = HW / NCHUNK;                     // 64
    const __nv_bfloat162* A = (const __nv_bfloat162*)(g_attn
        + (size_t)b * HW * DOWN + (size_t)ck * lsz * DOWN) + j2;
    float2 s0 = {0.f, 0.f}, s1 = {0.f, 0.f}, s2 = {0.f, 0.f}, s3 = {0.f, 0.f};
    #pragma unroll 4
    for (int l = 0; l < lsz; l += 4) {
        float2 a = __bfloat1622float2(A[(size_t)(l + 0) * (DOWN / 2)]);
        float2 bvv = __bfloat1622float2(A[(size_t)(l + 1) * (DOWN / 2)]);
        float2 c = __bfloat1622float2(A[(size_t)(l + 2) * (DOWN / 2)]);
        float2 d = __bfloat1622float2(A[(size_t)(l + 3) * (DOWN / 2)]);
        s0.x += a.x; s0.y += a.y;
        s1.x += bvv.x; s1.y += bvv.y;
        s2.x += c.x; s2.y += c.y;
        s3.x += d.x; s3.y += d.y;
    }
    float2 o;
    o.x = (s0.x + s1.x) + (s2.x + s3.x);
    o.y = (s0.y + s1.y) + (s2.y + s3.y);
    *(float2*)&g_ps[(b * NCHUNK + ck) * DOWN + j2 * 2] = o;
}

__global__ void k_stats2() {
    const int b = blockIdx.y;
    const int j = blockIdx.x * 256 + threadIdx.x;
    float S = 0.f;
    #pragma unroll 8
    for (int c = 0; c < NCHUNK; c++)
        S += g_ps[(b * NCHUNK + c) * DOWN + j];
    g_csumr[b * DOWN + j] = 1.f / S;
}

// ---------------- K4: applied = P @ (V/S) via mma.sync bf16 m16n8k16 -------------
__global__ __launch_bounds__(256, 2) void k_apply_mma() {
    __shared__ __nv_bfloat16 sP[128][40];   // [l][j in chunk]
    __shared__ __nv_bfloat16 sB[128][40];   // [c][j in chunk]

    const int b   = blockIdx.y;
    const int l0  = blockIdx.x * 128;
    const int tid = threadIdx.x;
    const int wid = tid >> 5;
    const int lane = tid & 31;
    const int qid = lane >> 2;
    const int qtr = lane & 3;
    const int wm = (wid >> 2) * 64;
    const int wn = (wid & 3) * 32;

    const __nv_bfloat16* A = g_attn + ((size_t)b * HW + l0) * DOWN;
    const float* V  = g_vp   + (size_t)b * (C2 * DOWN);
    const float* cs = g_csumr + b * DOWN;

    float acc[4][4][4] = {};

    for (int j0 = 0; j0 < DOWN; j0 += 32) {
        #pragma unroll
        for (int it = 0; it < 4; it++) {
            int idx = tid + it * 256;
            int l = idx >> 3, jq = (idx & 7) * 4;
            uint2 v = *(const uint2*)&A[(size_t)l * DOWN + j0 + jq];
            *(uint2*)&sP[l][jq] = v;
        }
        #pragma unroll
        for (int it = 0; it < 4; it++) {
            int idx = tid + it * 256;
            int c = idx & 127, j4 = idx >> 7;     // j4 in 0..7
            float4 s4 = *(const float4*)&cs[j0 + j4 * 4];
            __nv_bfloat162 p0 = __floats2bfloat162_rn(
                V[(size_t)(j0 + j4 * 4 + 0) * C2 + c] * s4.x,
                V[(size_t)(j0 + j4 * 4 + 1) * C2 + c] * s4.y);
            __nv_bfloat162 p1 = __floats2bfloat162_rn(
                V[(size_t)(j0 + j4 * 4 + 2) * C2 + c] * s4.z,
                V[(size_t)(j0 + j4 * 4 + 3) * C2 + c] * s4.w);
            uint2 o;
            o.x = *(uint32_t*)&p0;
            o.y = *(uint32_t*)&p1;
            *(uint2*)&sB[c][j4 * 4] = o;
        }
        __syncthreads();

        #pragma unroll
        for (int ks = 0; ks < 2; ks++) {
            const int kb = ks * 16;
            uint32_t bfr[4][2];
            #pragma unroll
            for (int na = 0; na < 4; na++) {
                int c = wn + na * 8 + qid;
                bfr[na][0] = *(const uint32_t*)&sB[c][kb + qtr * 2];
                bfr[na][1] = *(const uint32_t*)&sB[c][kb + 8 + qtr * 2];
            }
            #pragma unroll
            for (int ma = 0; ma < 4; ma++) {
                int r = wm + ma * 16 + qid;
                uint32_t af[4];
                af[0] = *(const uint32_t*)&sP[r    ][kb + qtr * 2];
                af[1] = *(const uint32_t*)&sP[r + 8][kb + qtr * 2];
                af[2] = *(const uint32_t*)&sP[r    ][kb + 8 + qtr * 2];
                af[3] = *(const uint32_t*)&sP[r + 8][kb + 8 + qtr * 2];
                #pragma unroll
                for (int na = 0; na < 4; na++)
                    mma_bf16(acc[ma][na], af, bfr[na]);
            }
        }
        __syncthreads();
    }

    float* O = g_app + ((size_t)b * HW + l0) * C2;
    #pragma unroll
    for (int ma = 0; ma < 4; ma++) {
        int r = wm + ma * 16 + qid;
        #pragma unroll
        for (int na = 0; na < 4; na++) {
            int c = wn + na * 8 + 2 * qtr;
            float2 lo, hi;
            lo.x = acc[ma][na][0]; lo.y = acc[ma][na][1];
            hi.x = acc[ma][na][2]; hi.y = acc[ma][na][3];
            *(float2*)&O[(size_t)r * C2 + c]       = lo;
            *(float2*)&O[(size_t)(r + 8) * C2 + c] = hi;
        }
    }
}

// ---------------- K5: out = gamma*(W2 @ applied_r + b2) + x via mma tf32 ---------
__global__ __launch_bounds__(256) void k_out_mma(const float* __restrict__ w2,
                                                 const float* __restrict__ b2,
                                                 const float* __restrict__ gamma,
                                                 const float* __restrict__ x,
                                                 float* __restrict__ out) {
    __shared__ float sA[64][36];
    __shared__ float sB[32][136];

    const int b  = blockIdx.z;
    const int m0 = blockIdx.y * 64;
    const int n0 = blockIdx.x * 128;
    const float* Bm = g_app + (size_t)b * (HW * C2);   // viewed [128][4096]

    const int tid  = threadIdx.x;
    const int wid  = tid >> 5;
    const int lane = tid & 31;
    const int qid  = lane >> 2;
    const int qtr  = lane & 3;
    const int wm   = (wid >> 2) * 32;
    const int wn   = (wid & 3) * 32;

    float acc[2][4][4] = {};

    for (int k0 = 0; k0 < C2; k0 += 32) {
        #pragma unroll
        for (int it = 0; it < 2; it++) {
            int f = tid + it * 256;
            int m = f >> 3, k4 = (f & 7) * 4;
            float4 a4 = *(const float4*)&w2[(m0 + m) * C2 + k0 + k4];
            uint32_t* dp = (uint32_t*)&sA[m][k4];
            dp[0] = f2tf32(a4.x); dp[1] = f2tf32(a4.y);
            dp[2] = f2tf32(a4.z); dp[3] = f2tf32(a4.w);
        }
        #pragma unroll
        for (int it = 0; it < 4; it++) {
            int f = tid + it * 256;
            int kk = f >> 5, n4 = (f & 31) * 4;
            float4 b4 = *(const float4*)&Bm[(size_t)(k0 + kk) * HW + n0 + n4];
            uint32_t* dp = (uint32_t*)&sB[kk][n4];
            dp[0] = f2tf32(b4.x); dp[1] = f2tf32(b4.y);
            dp[2] = f2tf32(b4.z); dp[3] = f2tf32(b4.w);
        }
        __syncthreads();

        #pragma unroll
        for (int ks = 0; ks < 4; ks++) {
            const int kk = ks * 8;
            uint32_t af[2][4], bf[4][2];
            #pragma unroll
            for (int ma = 0; ma < 2; ma++) {
                int r = wm + ma * 16 + qid;
                af[ma][0] = FU(sA[r    ][kk + qtr]);
                af[ma][1] = FU(sA[r + 8][kk + qtr]);
                af[ma][2] = FU(sA[r    ][kk + qtr + 4]);
                af[ma][3] = FU(sA[r + 8][kk + qtr + 4]);
            }
            #pragma unroll
            for (int na = 0; na < 4; na++) {
                int c = wn + na * 8 + qid;
                bf[na][0] = FU(sB[kk + qtr    ][c]);
                bf[na][1] = FU(sB[kk + qtr + 4][c]);
            }
            #pragma unroll
            for (int ma = 0; ma < 2; ma++)
                #pragma unroll
                for (int na = 0; na < 4; na++)
                    mma_tf32(acc[ma][na], af[ma], bf[na]);
        }
        __syncthreads();
    }

    const float g = __ldg(gamma);
    #pragma unroll
    for (int ma = 0; ma < 2; ma++) {
        #pragma unroll
        for (int half = 0; half < 2; half++) {
            int m = m0 + wm + ma * 16 + qid + half * 8;
            float bias = b2[m];
            #pragma unroll
            for (int na = 0; na < 4; na++) {
                int c = n0 + wn + na * 8 + 2 * qtr;
                size_t base = ((size_t)b * 256 + m) * HW + c;
                float2 xi = *(const float2*)&x[base];
                float2 o;
                o.x = g * (acc[ma][na][half * 2 + 0] + bias) + xi.x;
                o.y = g * (acc[ma][na][half * 2 + 1] + bias) + xi.y;
                *(float2*)&out[base] = o;
            }
        }
    }
}

// ---------------- launch ---------------------------------------------------------
extern "C" void kernel_launch(void* const* d_in, const int* in_sizes, int n_in,
                              void* d_out, int out_size) {
    const float* x  = (const float*)d_in[0];
    const float* qw = (const float*)d_in[1];
    const float* qb = (const float*)d_in[2];
    const float* kw = (const float*)d_in[3];
    const float* kb = (const float*)d_in[4];
    const float* vw = (const float*)d_in[5];
    const float* vb = (const float*)d_in[6];
    const float* w2 = (const float*)d_in[7];
    const float* b2 = (const float*)d_in[8];
    const float* gm = (const float*)d_in[9];
    float* out = (float*)d_out;

    k_pack<<<(MCONV * CIN + 255) / 256, 256>>>(qw, qb, kw, kb, vw, vb);
    k_conv_mma<<<dim3(HW / 128, MCONV / 64, BATCH), 256>>>(x);
    k_attn_mma<<<dim3(DOWN / 128, HW / 64, BATCH), 256>>>();
    k_stats1<<<dim3(DOWN / 2 / 256, NCHUNK, BATCH), 256>>>();
    k_stats2<<<dim3(DOWN / 256, BATCH), 256>>>();
    k_apply_mma<<<dim3(HW / 128, BATCH), 256>>>();
    k_out_mma<<<dim3(HW / 128, 256 / 64, BATCH), 256>>>(w2, b2, gm, x, out);
}